// round 6
// baseline (speedup 1.0000x reference)
#include <cuda_runtime.h>
#include <cuda_bf16.h>
#include <cuda_fp8.h>
#include <cstdint>

#define NUM_MEM 4096
#define MEM_DIM 512
#define INP_DIM 1024
#define NQ      32768

// ---------------- scratch (static device globals; no allocs) ----------------
__device__ uint8_t       g_kf8  [(size_t)NQ * INP_DIM];       // 32 MB (e4m3 k)
__device__ __nv_bfloat16 g_membf[(size_t)NUM_MEM * MEM_DIM];  // 4 MB
__device__ __nv_bfloat16 g_fkw  [(size_t)INP_DIM * MEM_DIM];  // 1 MB
__device__ __nv_bfloat16 g_fvw  [(size_t)INP_DIM * MEM_DIM];  // 1 MB
__device__ float         g_keylog[(size_t)NUM_MEM * INP_DIM]; // 16 MB
__device__ uint8_t       g_keyf8[(size_t)NUM_MEM * INP_DIM];  // 4 MB (e4m3 key*512)
__device__ __nv_bfloat16 g_valT [(size_t)INP_DIM * NUM_MEM];  // 8 MB (val transposed, K-major)
__device__ __nv_bfloat16 g_S    [(size_t)NQ * NUM_MEM];       // 256 MB (512*logits -> att, in place)

// ---------------- helpers ----------------
__device__ __forceinline__ uint32_t smem_u32(const void* p) {
    return (uint32_t)__cvta_generic_to_shared(p);
}
__device__ __forceinline__ void cp_async16(uint32_t dst, const void* src) {
    asm volatile("cp.async.cg.shared.global [%0], [%1], 16;\n" :: "r"(dst), "l"(src) : "memory");
}
__device__ __forceinline__ void cp_commit() {
    asm volatile("cp.async.commit_group;\n" ::: "memory");
}
template<int N> __device__ __forceinline__ void cp_wait() {
    asm volatile("cp.async.wait_group %0;\n" :: "n"(N) : "memory");
}

// ---------------- converts ----------------
__global__ void f32_to_bf16_kernel(const float* __restrict__ in,
                                   __nv_bfloat16* __restrict__ out, int n4) {
    int i = blockIdx.x * blockDim.x + threadIdx.x;
    if (i < n4) {
        float4 v = reinterpret_cast<const float4*>(in)[i];
        __nv_bfloat162* o = reinterpret_cast<__nv_bfloat162*>(out) + i * 2;
        o[0] = __floats2bfloat162_rn(v.x, v.y);
        o[1] = __floats2bfloat162_rn(v.z, v.w);
    }
}
__global__ void f32_to_e4m3_kernel(const float* __restrict__ in,
                                   uint8_t* __restrict__ out, int n4) {
    int i = blockIdx.x * blockDim.x + threadIdx.x;
    if (i < n4) {
        float4 v = reinterpret_cast<const float4*>(in)[i];
        __nv_fp8x4_e4m3 p(v);
        reinterpret_cast<uint32_t*>(out)[i] = *reinterpret_cast<uint32_t*>(&p);
    }
}

// =====================================================================
// FP8 e4m3 TN GEMM (mma.sync m16n8k32): C[M,N] = A[M,K] * B[N,K]^T, bf16 out.
// BM=128, BN=256, BK=128 (elems = bytes), 4-stage, 8 warps, warp tile 64x64.
// Byte-identical smem addressing to the bf16 version (128B rows, 16B-chunk swizzle).
// =====================================================================
#define BBM 128
#define BBN 256
#define BSTAGES 4
#define BA_BYTES (BBM * 128)                 // 16 KB
#define BB_BYTES (BBN * 128)                 // 32 KB
#define BSTAGE_BYTES (BA_BYTES + BB_BYTES)   // 48 KB
#define BDSMEM (BSTAGES * BSTAGE_BYTES)      // 192 KB

__global__ __launch_bounds__(256, 1)
void gemm_s_fp8(const uint8_t* __restrict__ A, const uint8_t* __restrict__ B,
                int K, __nv_bfloat16* __restrict__ Cout, int ldc)
{
    extern __shared__ __align__(128) char dsm[];
    const uint32_t sbase = smem_u32(dsm);

    const int tid  = threadIdx.x;
    const int lane = tid & 31;
    const int warp = tid >> 5;
    const int wm = warp >> 2;
    const int wn = warp & 3;
    const int bm = blockIdx.y * BBM;
    const int bn = blockIdx.x * BBN;

    float acc[4][8][4];
#pragma unroll
    for (int i = 0; i < 4; i++)
#pragma unroll
        for (int j = 0; j < 8; j++)
#pragma unroll
            for (int q = 0; q < 4; q++) acc[i][j][q] = 0.f;

    const int KT = K / 128;   // 128 fp8 elems per tile row (128B)

    auto load_tile = [&](int st, int kt) {
        const uint32_t a_s = sbase + st * BSTAGE_BYTES;
        const uint32_t b_s = a_s + BA_BYTES;
        const int kk = kt * 128;
#pragma unroll
        for (int g = 0; g < 4; g++) {
            int idx = tid + g * 256;
            int r = idx >> 3, c = idx & 7;
            cp_async16(a_s + r * 128 + ((c ^ (r & 7)) << 4),
                       A + (size_t)(bm + r) * K + kk + c * 16);
        }
#pragma unroll
        for (int g = 0; g < 8; g++) {
            int idx = tid + g * 256;
            int r = idx >> 3, c = idx & 7;
            cp_async16(b_s + r * 128 + ((c ^ (r & 7)) << 4),
                       B + (size_t)(bn + r) * K + kk + c * 16);
        }
        cp_commit();
    };

    load_tile(0, 0);
    load_tile(1, 1);
    load_tile(2, 2);
    load_tile(3, 3);

    for (int kt = 0; kt < KT; ++kt) {
        const int st = kt & 3;
        cp_wait<BSTAGES - 1>();
        __syncthreads();

        const uint32_t a_s = sbase + st * BSTAGE_BYTES;
        const uint32_t b_s = a_s + BA_BYTES;

#pragma unroll
        for (int ks = 0; ks < 4; ++ks) {   // each ks = k32 fp8 = 32B
            uint32_t a[4][4];
#pragma unroll
            for (int mi = 0; mi < 4; mi++) {
                int row = wm * 64 + mi * 16 + (lane & 15);
                int c = ks * 2 + (lane >> 4);
                uint32_t addr = a_s + row * 128 + ((c ^ (row & 7)) << 4);
                asm volatile("ldmatrix.sync.aligned.m8n8.x4.shared.b16 {%0,%1,%2,%3}, [%4];\n"
                             : "=r"(a[mi][0]), "=r"(a[mi][1]), "=r"(a[mi][2]), "=r"(a[mi][3])
                             : "r"(addr));
            }
            uint32_t b[8][2];
#pragma unroll
            for (int nb = 0; nb < 4; nb++) {
                int row = wn * 64 + nb * 16 + (lane & 7) + ((lane >> 4) << 3);
                int c = ks * 2 + ((lane >> 3) & 1);
                uint32_t addr = b_s + row * 128 + ((c ^ (row & 7)) << 4);
                asm volatile("ldmatrix.sync.aligned.m8n8.x4.shared.b16 {%0,%1,%2,%3}, [%4];\n"
                             : "=r"(b[nb * 2][0]), "=r"(b[nb * 2][1]),
                               "=r"(b[nb * 2 + 1][0]), "=r"(b[nb * 2 + 1][1])
                             : "r"(addr));
            }
#pragma unroll
            for (int mi = 0; mi < 4; mi++)
#pragma unroll
                for (int ni = 0; ni < 8; ni++)
                    asm volatile("mma.sync.aligned.m16n8k32.row.col.f32.e4m3.e4m3.f32 "
                                 "{%0,%1,%2,%3}, {%4,%5,%6,%7}, {%8,%9}, {%0,%1,%2,%3};\n"
                                 : "+f"(acc[mi][ni][0]), "+f"(acc[mi][ni][1]),
                                   "+f"(acc[mi][ni][2]), "+f"(acc[mi][ni][3])
                                 : "r"(a[mi][0]), "r"(a[mi][1]), "r"(a[mi][2]), "r"(a[mi][3]),
                                   "r"(b[ni][0]), "r"(b[ni][1]));
        }

        __syncthreads();
        if (kt + BSTAGES < KT) load_tile(st, kt + BSTAGES);
    }

    const int gid = lane >> 2, tg = lane & 3;
#pragma unroll
    for (int mi = 0; mi < 4; mi++) {
#pragma unroll
        for (int ni = 0; ni < 8; ni++) {
            int row = bm + wm * 64 + mi * 16 + gid;
            int col = bn + wn * 64 + ni * 8 + tg * 2;
            *reinterpret_cast<__nv_bfloat162*>(&Cout[(size_t)row * ldc + col]) =
                __floats2bfloat162_rn(acc[mi][ni][0], acc[mi][ni][1]);
            *reinterpret_cast<__nv_bfloat162*>(&Cout[(size_t)(row + 8) * ldc + col]) =
                __floats2bfloat162_rn(acc[mi][ni][2], acc[mi][ni][3]);
        }
    }
}

// =====================================================================
// Big bf16 TN GEMM (mma.sync): C = A * B^T. BM=128, BN=256, BK=64, 4-stage.
// mode 0: bf16 store.  mode 1: fp32 store.  (R5 winner, unchanged)
// =====================================================================
#define BBK 64

__global__ __launch_bounds__(256, 1)
void gemm_big(const __nv_bfloat16* __restrict__ A, const __nv_bfloat16* __restrict__ B,
              int K, int mode, void* __restrict__ Cout, int ldc)
{
    extern __shared__ __align__(128) char dsm[];
    const uint32_t sbase = smem_u32(dsm);

    const int tid  = threadIdx.x;
    const int lane = tid & 31;
    const int warp = tid >> 5;
    const int wm = warp >> 2;
    const int wn = warp & 3;
    const int bm = blockIdx.y * BBM;
    const int bn = blockIdx.x * BBN;

    float acc[4][8][4];
#pragma unroll
    for (int i = 0; i < 4; i++)
#pragma unroll
        for (int j = 0; j < 8; j++)
#pragma unroll
            for (int q = 0; q < 4; q++) acc[i][j][q] = 0.f;

    const int KT = K / BBK;

    auto load_tile = [&](int st, int kt) {
        const uint32_t a_s = sbase + st * BSTAGE_BYTES;
        const uint32_t b_s = a_s + BA_BYTES;
        const int kk = kt * BBK;
#pragma unroll
        for (int g = 0; g < 4; g++) {
            int idx = tid + g * 256;
            int r = idx >> 3, c = idx & 7;
            cp_async16(a_s + r * 128 + ((c ^ (r & 7)) << 4),
                       A + (size_t)(bm + r) * K + kk + c * 8);
        }
#pragma unroll
        for (int g = 0; g < 8; g++) {
            int idx = tid + g * 256;
            int r = idx >> 3, c = idx & 7;
            cp_async16(b_s + r * 128 + ((c ^ (r & 7)) << 4),
                       B + (size_t)(bn + r) * K + kk + c * 8);
        }
        cp_commit();
    };

    load_tile(0, 0);
    load_tile(1, 1);
    load_tile(2, 2);
    load_tile(3, 3);

    for (int kt = 0; kt < KT; ++kt) {
        const int st = kt & 3;
        cp_wait<BSTAGES - 1>();
        __syncthreads();

        const uint32_t a_s = sbase + st * BSTAGE_BYTES;
        const uint32_t b_s = a_s + BA_BYTES;

#pragma unroll
        for (int ks = 0; ks < 4; ++ks) {
            uint32_t a[4][4];
#pragma unroll
            for (int mi = 0; mi < 4; mi++) {
                int row = wm * 64 + mi * 16 + (lane & 15);
                int c = ks * 2 + (lane >> 4);
                uint32_t addr = a_s + row * 128 + ((c ^ (row & 7)) << 4);
                asm volatile("ldmatrix.sync.aligned.m8n8.x4.shared.b16 {%0,%1,%2,%3}, [%4];\n"
                             : "=r"(a[mi][0]), "=r"(a[mi][1]), "=r"(a[mi][2]), "=r"(a[mi][3])
                             : "r"(addr));
            }
            uint32_t b[8][2];
#pragma unroll
            for (int nb = 0; nb < 4; nb++) {
                int row = wn * 64 + nb * 16 + (lane & 7) + ((lane >> 4) << 3);
                int c = ks * 2 + ((lane >> 3) & 1);
                uint32_t addr = b_s + row * 128 + ((c ^ (row & 7)) << 4);
                asm volatile("ldmatrix.sync.aligned.m8n8.x4.shared.b16 {%0,%1,%2,%3}, [%4];\n"
                             : "=r"(b[nb * 2][0]), "=r"(b[nb * 2][1]),
                               "=r"(b[nb * 2 + 1][0]), "=r"(b[nb * 2 + 1][1])
                             : "r"(addr));
            }
#pragma unroll
            for (int mi = 0; mi < 4; mi++)
#pragma unroll
                for (int ni = 0; ni < 8; ni++)
                    asm volatile("mma.sync.aligned.m16n8k16.row.col.f32.bf16.bf16.f32 "
                                 "{%0,%1,%2,%3}, {%4,%5,%6,%7}, {%8,%9}, {%0,%1,%2,%3};\n"
                                 : "+f"(acc[mi][ni][0]), "+f"(acc[mi][ni][1]),
                                   "+f"(acc[mi][ni][2]), "+f"(acc[mi][ni][3])
                                 : "r"(a[mi][0]), "r"(a[mi][1]), "r"(a[mi][2]), "r"(a[mi][3]),
                                   "r"(b[ni][0]), "r"(b[ni][1]));
        }

        __syncthreads();
        if (kt + BSTAGES < KT) load_tile(st, kt + BSTAGES);
    }

    const int gid = lane >> 2, tg = lane & 3;
#pragma unroll
    for (int mi = 0; mi < 4; mi++) {
#pragma unroll
        for (int ni = 0; ni < 8; ni++) {
            int row = bm + wm * 64 + mi * 16 + gid;
            int col = bn + wn * 64 + ni * 8 + tg * 2;
            float v0 = acc[mi][ni][0], v1 = acc[mi][ni][1];
            float v2 = acc[mi][ni][2], v3 = acc[mi][ni][3];
            if (mode == 0) {
                __nv_bfloat16* C = (__nv_bfloat16*)Cout;
                *reinterpret_cast<__nv_bfloat162*>(&C[(size_t)row * ldc + col]) =
                    __floats2bfloat162_rn(v0, v1);
                *reinterpret_cast<__nv_bfloat162*>(&C[(size_t)(row + 8) * ldc + col]) =
                    __floats2bfloat162_rn(v2, v3);
            } else {
                float* C = (float*)Cout;
                C[(size_t)row * ldc + col]           = v0;
                C[(size_t)row * ldc + col + 1]       = v1;
                C[(size_t)(row + 8) * ldc + col]     = v2;
                C[(size_t)(row + 8) * ldc + col + 1] = v3;
            }
        }
    }
}

// ---------------- generic bf16 TN GEMM (mma.sync) for the small prep GEMMs ----------------
#define GBM 128
#define GBN 128
#define GBK 32
#define SSTR 48

__global__ __launch_bounds__(256)
void gemm_tn(const __nv_bfloat16* __restrict__ A, const __nv_bfloat16* __restrict__ B,
             int M, int N, int K, const float* __restrict__ bias, int mode,
             void* __restrict__ Cout, int ldc)
{
    __shared__ __nv_bfloat16 sA[2][GBM * SSTR];
    __shared__ __nv_bfloat16 sB[2][GBN * SSTR];

    const int tid  = threadIdx.x;
    const int lane = tid & 31;
    const int warp = tid >> 5;
    const int wm = warp >> 1;
    const int wn = warp & 1;
    const int bm = blockIdx.y * GBM;
    const int bn = blockIdx.x * GBN;

    const int c0 = tid, c1 = tid + 256;
    const int r0 = c0 >> 2, cc0 = (c0 & 3) * 8;
    const int r1 = c1 >> 2, cc1 = (c1 & 3) * 8;

    float acc[2][8][4];
#pragma unroll
    for (int i = 0; i < 2; i++)
#pragma unroll
        for (int j = 0; j < 8; j++)
#pragma unroll
            for (int q = 0; q < 4; q++) acc[i][j][q] = 0.f;

    const int KT = K / GBK;
    {
        cp_async16(smem_u32(&sA[0][r0 * SSTR + cc0]), A + (size_t)(bm + r0) * K + cc0);
        cp_async16(smem_u32(&sA[0][r1 * SSTR + cc1]), A + (size_t)(bm + r1) * K + cc1);
        cp_async16(smem_u32(&sB[0][r0 * SSTR + cc0]), B + (size_t)(bn + r0) * K + cc0);
        cp_async16(smem_u32(&sB[0][r1 * SSTR + cc1]), B + (size_t)(bn + r1) * K + cc1);
        cp_commit();
    }

    for (int kt = 0; kt < KT; ++kt) {
        const int buf = kt & 1;
        if (kt + 1 < KT) {
            const int k0 = (kt + 1) * GBK;
            const int nb = buf ^ 1;
            cp_async16(smem_u32(&sA[nb][r0 * SSTR + cc0]), A + (size_t)(bm + r0) * K + k0 + cc0);
            cp_async16(smem_u32(&sA[nb][r1 * SSTR + cc1]), A + (size_t)(bm + r1) * K + k0 + cc1);
            cp_async16(smem_u32(&sB[nb][r0 * SSTR + cc0]), B + (size_t)(bn + r0) * K + k0 + cc0);
            cp_async16(smem_u32(&sB[nb][r1 * SSTR + cc1]), B + (size_t)(bn + r1) * K + k0 + cc1);
            cp_commit();
            cp_wait<1>();
        } else {
            cp_wait<0>();
        }
        __syncthreads();

#pragma unroll
        for (int ks = 0; ks < 2; ++ks) {
            uint32_t a[2][4];
#pragma unroll
            for (int mi = 0; mi < 2; mi++) {
                uint32_t addr = smem_u32(&sA[buf][(wm * 32 + mi * 16 + (lane & 15)) * SSTR
                                                  + ks * 16 + (lane >> 4) * 8]);
                asm volatile("ldmatrix.sync.aligned.m8n8.x4.shared.b16 {%0,%1,%2,%3}, [%4];\n"
                             : "=r"(a[mi][0]), "=r"(a[mi][1]), "=r"(a[mi][2]), "=r"(a[mi][3])
                             : "r"(addr));
            }
            uint32_t b[8][2];
#pragma unroll
            for (int nb2 = 0; nb2 < 4; nb2++) {
                int nrow = wn * 64 + nb2 * 16 + (lane & 7) + ((lane >> 4) << 3);
                int kcol = ks * 16 + (((lane >> 3) & 1) << 3);
                uint32_t addr = smem_u32(&sB[buf][nrow * SSTR + kcol]);
                asm volatile("ldmatrix.sync.aligned.m8n8.x4.shared.b16 {%0,%1,%2,%3}, [%4];\n"
                             : "=r"(b[nb2 * 2][0]), "=r"(b[nb2 * 2][1]),
                               "=r"(b[nb2 * 2 + 1][0]), "=r"(b[nb2 * 2 + 1][1])
                             : "r"(addr));
            }
#pragma unroll
            for (int mi = 0; mi < 2; mi++)
#pragma unroll
                for (int ni = 0; ni < 8; ni++)
                    asm volatile("mma.sync.aligned.m16n8k16.row.col.f32.bf16.bf16.f32 "
                                 "{%0,%1,%2,%3}, {%4,%5,%6,%7}, {%8,%9}, {%0,%1,%2,%3};\n"
                                 : "+f"(acc[mi][ni][0]), "+f"(acc[mi][ni][1]),
                                   "+f"(acc[mi][ni][2]), "+f"(acc[mi][ni][3])
                                 : "r"(a[mi][0]), "r"(a[mi][1]), "r"(a[mi][2]), "r"(a[mi][3]),
                                   "r"(b[ni][0]), "r"(b[ni][1]));
        }
        __syncthreads();
    }

    const int gid = lane >> 2, tg = lane & 3;
#pragma unroll
    for (int mi = 0; mi < 2; mi++) {
#pragma unroll
        for (int ni = 0; ni < 8; ni++) {
            int row = bm + wm * 32 + mi * 16 + gid;
            int col = bn + wn * 64 + ni * 8 + tg * 2;
            float v0 = acc[mi][ni][0], v1 = acc[mi][ni][1];
            float v2 = acc[mi][ni][2], v3 = acc[mi][ni][3];
            if (mode == 1) {
                float* C = (float*)Cout;
                float b0 = bias ? bias[col] : 0.f;
                float b1 = bias ? bias[col + 1] : 0.f;
                C[(size_t)row * ldc + col]           = v0 + b0;
                C[(size_t)row * ldc + col + 1]       = v1 + b1;
                C[(size_t)(row + 8) * ldc + col]     = v2 + b0;
                C[(size_t)(row + 8) * ldc + col + 1] = v3 + b1;
            } else {  // mode 2: relu(C + bias), transposed bf16 store
                __nv_bfloat16* C = (__nv_bfloat16*)Cout;
                float b0 = bias[col], b1 = bias[col + 1];
                C[(size_t)col * ldc + row]           = __float2bfloat16(fmaxf(v0 + b0, 0.f));
                C[(size_t)(col + 1) * ldc + row]     = __float2bfloat16(fmaxf(v1 + b1, 0.f));
                C[(size_t)col * ldc + row + 8]       = __float2bfloat16(fmaxf(v2 + b0, 0.f));
                C[(size_t)(col + 1) * ldc + row + 8] = __float2bfloat16(fmaxf(v3 + b1, 0.f));
            }
        }
    }
}

// ---------------- block reduction helpers ----------------
__device__ __forceinline__ float block_reduce_max(float v, float* sred) {
#pragma unroll
    for (int o = 16; o > 0; o >>= 1) v = fmaxf(v, __shfl_xor_sync(0xffffffffu, v, o));
    if ((threadIdx.x & 31) == 0) sred[threadIdx.x >> 5] = v;
    __syncthreads();
    if (threadIdx.x == 0) {
        float m = sred[0];
        for (int w = 1; w < (int)(blockDim.x >> 5); w++) m = fmaxf(m, sred[w]);
        sred[0] = m;
    }
    __syncthreads();
    float r = sred[0];
    __syncthreads();
    return r;
}
__device__ __forceinline__ float block_reduce_sum(float v, float* sred) {
#pragma unroll
    for (int o = 16; o > 0; o >>= 1) v += __shfl_xor_sync(0xffffffffu, v, o);
    if ((threadIdx.x & 31) == 0) sred[threadIdx.x >> 5] = v;
    __syncthreads();
    if (threadIdx.x == 0) {
        float s = sred[0];
        for (int w = 1; w < (int)(blockDim.x >> 5); w++) s += sred[w];
        sred[0] = s;
    }
    __syncthreads();
    float r = sred[0];
    __syncthreads();
    return r;
}

// ---------------- softmax: fp32 logits row -> e4m3 (key derivation), scaled x512 ----------
__global__ __launch_bounds__(256)
void softmax_f32_fp8(const float* __restrict__ in, uint8_t* __restrict__ out, int ncol) {
    __shared__ float sred[8];
    const float* x = in + (size_t)blockIdx.x * ncol;
    uint8_t* o = out + (size_t)blockIdx.x * ncol;
    float m = -1e30f;
    for (int i = threadIdx.x; i < ncol; i += blockDim.x) m = fmaxf(m, x[i]);
    m = block_reduce_max(m, sred);
    float s = 0.f;
    for (int i = threadIdx.x; i < ncol; i += blockDim.x) s += __expf(x[i] - m);
    s = block_reduce_sum(s, sred);
    float inv = 512.f / s;   // fold the x512 fp8-range scale into the normalization
    for (int i = threadIdx.x; i < ncol; i += blockDim.x) {
        __nv_fp8_e4m3 p(__expf(x[i] - m) * inv);
        o[i] = *reinterpret_cast<uint8_t*>(&p);
    }
}

// ---------------- softmax: bf16 row in-place, register-resident; input = 512*logits ----
__global__ __launch_bounds__(256)
void softmax_bf16_inplace(__nv_bfloat16* __restrict__ S) {
    __shared__ float sred[8];
    uint4* row = reinterpret_cast<uint4*>(S + (size_t)blockIdx.x * NUM_MEM);
    uint4 v0 = row[threadIdx.x * 2];
    uint4 v1 = row[threadIdx.x * 2 + 1];
    float f[16];
    const float descale = 1.f / 512.f;
    {
        const __nv_bfloat162* p0 = reinterpret_cast<const __nv_bfloat162*>(&v0);
        const __nv_bfloat162* p1 = reinterpret_cast<const __nv_bfloat162*>(&v1);
#pragma unroll
        for (int i = 0; i < 4; i++) {
            float2 a = __bfloat1622float2(p0[i]);
            float2 b = __bfloat1622float2(p1[i]);
            f[2 * i] = a.x * descale; f[2 * i + 1] = a.y * descale;
            f[8 + 2 * i] = b.x * descale; f[8 + 2 * i + 1] = b.y * descale;
        }
    }
    float m = -1e30f;
#pragma unroll
    for (int i = 0; i < 16; i++) m = fmaxf(m, f[i]);
    m = block_reduce_max(m, sred);
    float s = 0.f;
#pragma unroll
    for (int i = 0; i < 16; i++) { f[i] = __expf(f[i] - m); s += f[i]; }
    s = block_reduce_sum(s, sred);
    float inv = 1.f / s;
    {
        __nv_bfloat162* p0 = reinterpret_cast<__nv_bfloat162*>(&v0);
        __nv_bfloat162* p1 = reinterpret_cast<__nv_bfloat162*>(&v1);
#pragma unroll
        for (int i = 0; i < 4; i++) {
            p0[i] = __floats2bfloat162_rn(f[2 * i] * inv, f[2 * i + 1] * inv);
            p1[i] = __floats2bfloat162_rn(f[8 + 2 * i] * inv, f[8 + 2 * i + 1] * inv);
        }
    }
    row[threadIdx.x * 2] = v0;
    row[threadIdx.x * 2 + 1] = v1;
}

// ---------------- launch ----------------
extern "C" void kernel_launch(void* const* d_in, const int* in_sizes, int n_in,
                              void* d_out, int out_size) {
    const float* k    = (const float*)d_in[0];
    const float* mem  = (const float*)d_in[1];
    const float* fk_w = (const float*)d_in[2];
    const float* fk_b = (const float*)d_in[3];
    const float* fv_w = (const float*)d_in[4];
    const float* fv_b = (const float*)d_in[5];
    float* out = (float*)d_out;

    void *p_kf8, *p_membf, *p_fkw, *p_fvw, *p_keylog, *p_keyf8, *p_valT, *p_S;
    cudaGetSymbolAddress(&p_kf8, g_kf8);
    cudaGetSymbolAddress(&p_membf, g_membf);
    cudaGetSymbolAddress(&p_fkw, g_fkw);
    cudaGetSymbolAddress(&p_fvw, g_fvw);
    cudaGetSymbolAddress(&p_keylog, g_keylog);
    cudaGetSymbolAddress(&p_keyf8, g_keyf8);
    cudaGetSymbolAddress(&p_valT, g_valT);
    cudaGetSymbolAddress(&p_S, g_S);

    uint8_t*       kf8    = (uint8_t*)p_kf8;
    __nv_bfloat16* membf  = (__nv_bfloat16*)p_membf;
    __nv_bfloat16* fkwbf  = (__nv_bfloat16*)p_fkw;
    __nv_bfloat16* fvwbf  = (__nv_bfloat16*)p_fvw;
    float*         keylog = (float*)p_keylog;
    uint8_t*       keyf8  = (uint8_t*)p_keyf8;
    __nv_bfloat16* valT   = (__nv_bfloat16*)p_valT;
    __nv_bfloat16* S      = (__nv_bfloat16*)p_S;

    cudaFuncSetAttribute(gemm_big, cudaFuncAttributeMaxDynamicSharedMemorySize, BDSMEM);
    cudaFuncSetAttribute(gemm_s_fp8, cudaFuncAttributeMaxDynamicSharedMemorySize, BDSMEM);

    // converts
    {
        int n4 = NQ * INP_DIM / 4;
        f32_to_e4m3_kernel<<<(n4 + 255) / 256, 256>>>(k, kf8, n4);
        n4 = NUM_MEM * MEM_DIM / 4;
        f32_to_bf16_kernel<<<(n4 + 255) / 256, 256>>>(mem, membf, n4);
        n4 = INP_DIM * MEM_DIM / 4;
        f32_to_bf16_kernel<<<(n4 + 255) / 256, 256>>>(fk_w, fkwbf, n4);
        f32_to_bf16_kernel<<<(n4 + 255) / 256, 256>>>(fv_w, fvwbf, n4);
    }

    // prep: key logits (fp32 + bias), val = relu -> transposed bf16
    {
        dim3 grid(INP_DIM / GBN, NUM_MEM / GBM);
        gemm_tn<<<grid, 256>>>(membf, fkwbf, NUM_MEM, INP_DIM, MEM_DIM, fk_b, 1, keylog, INP_DIM);
        gemm_tn<<<grid, 256>>>(membf, fvwbf, NUM_MEM, INP_DIM, MEM_DIM, fv_b, 2, valT, NUM_MEM);
    }
    softmax_f32_fp8<<<NUM_MEM, 256>>>(keylog, keyf8, INP_DIM);

    // S = k @ key^T   [32768, 4096], fp8 operands, result = 512 * logits (bf16)
    {
        dim3 grid(NUM_MEM / BBN, NQ / BBM);   // (16, 256)
        gemm_s_fp8<<<grid, 256, BDSMEM>>>(kf8, keyf8, INP_DIM, S, NUM_MEM);
    }

    // att = softmax(S / 512) row-wise, in place
    softmax_bf16_inplace<<<NQ, 256>>>(S);

    // out = att @ valT^T   [32768, 1024]
    {
        dim3 grid(INP_DIM / BBN, NQ / BBM);   // (4, 256)
        gemm_big<<<grid, 256, BDSMEM>>>(S, valT, NUM_MEM, 1, out, INP_DIM);
    }
}

// round 7
// speedup vs baseline: 1.1047x; 1.1047x over previous
#include <cuda_runtime.h>
#include <cuda_bf16.h>
#include <cstdint>

#define NUM_MEM 4096
#define MEM_DIM 512
#define INP_DIM 1024
#define NQ      32768

// ---------------- scratch (static device globals; no allocs) ----------------
__device__ __nv_bfloat16 g_kbf  [(size_t)NQ * INP_DIM];       // 64 MB
__device__ __nv_bfloat16 g_membf[(size_t)NUM_MEM * MEM_DIM];  // 4 MB
__device__ __nv_bfloat16 g_fkw  [(size_t)INP_DIM * MEM_DIM];  // 1 MB
__device__ __nv_bfloat16 g_fvw  [(size_t)INP_DIM * MEM_DIM];  // 1 MB
__device__ float         g_keylog[(size_t)NUM_MEM * INP_DIM]; // 16 MB
__device__ __nv_bfloat16 g_key  [(size_t)NUM_MEM * INP_DIM];  // 8 MB
__device__ __nv_bfloat16 g_valT [(size_t)INP_DIM * NUM_MEM];  // 8 MB (val transposed, K-major)
__device__ __nv_bfloat16 g_S    [(size_t)NQ * NUM_MEM];       // 256 MB (E = exp(logits))
__device__ float         g_rowsum[(size_t)NQ];                // 128 KB (softmax denominators)

// ---------------- helpers ----------------
__device__ __forceinline__ uint32_t smem_u32(const void* p) {
    return (uint32_t)__cvta_generic_to_shared(p);
}
__device__ __forceinline__ void cp_async16(uint32_t dst, const void* src) {
    asm volatile("cp.async.cg.shared.global [%0], [%1], 16;\n" :: "r"(dst), "l"(src) : "memory");
}
__device__ __forceinline__ void cp_commit() {
    asm volatile("cp.async.commit_group;\n" ::: "memory");
}
template<int N> __device__ __forceinline__ void cp_wait() {
    asm volatile("cp.async.wait_group %0;\n" :: "n"(N) : "memory");
}

// ---------------- fp32 -> bf16 convert ----------------
__global__ void f32_to_bf16_kernel(const float* __restrict__ in,
                                   __nv_bfloat16* __restrict__ out, int n4) {
    int i = blockIdx.x * blockDim.x + threadIdx.x;
    if (i < n4) {
        float4 v = reinterpret_cast<const float4*>(in)[i];
        __nv_bfloat162* o = reinterpret_cast<__nv_bfloat162*>(out) + i * 2;
        o[0] = __floats2bfloat162_rn(v.x, v.y);
        o[1] = __floats2bfloat162_rn(v.z, v.w);
    }
}

__global__ void zero_f32_kernel(float* __restrict__ p, int n) {
    int i = blockIdx.x * blockDim.x + threadIdx.x;
    if (i < n) p[i] = 0.f;
}

// =====================================================================
// Big bf16 TN GEMM (mma.sync): C[M,N] = A[M,K] * B[N,K]^T
// BM=128, BN=256, BK=64, 4-stage cp.async, 8 warps (2m x 4n), warp tile 64x64.
// mode 1: fp32 store, scaled by 1/rs[row] if rs != nullptr.
// mode 2: E = exp(C) -> bf16 store + atomicAdd per-row sums into rs.
// =====================================================================
#define BBM 128
#define BBN 256
#define BBK 64
#define BSTAGES 4
#define BA_BYTES (BBM * 128)                 // 16 KB
#define BB_BYTES (BBN * 128)                 // 32 KB
#define BSTAGE_BYTES (BA_BYTES + BB_BYTES)   // 48 KB
#define BDSMEM (BSTAGES * BSTAGE_BYTES)      // 192 KB

__global__ __launch_bounds__(256, 1)
void gemm_big(const __nv_bfloat16* __restrict__ A, const __nv_bfloat16* __restrict__ B,
              int K, float* __restrict__ rs, int mode, void* __restrict__ Cout, int ldc)
{
    extern __shared__ __align__(128) char dsm[];
    const uint32_t sbase = smem_u32(dsm);

    const int tid  = threadIdx.x;
    const int lane = tid & 31;
    const int warp = tid >> 5;
    const int wm = warp >> 2;       // 0..1
    const int wn = warp & 3;        // 0..3
    const int bm = blockIdx.y * BBM;
    const int bn = blockIdx.x * BBN;

    float acc[4][8][4];
#pragma unroll
    for (int i = 0; i < 4; i++)
#pragma unroll
        for (int j = 0; j < 8; j++)
#pragma unroll
            for (int q = 0; q < 4; q++) acc[i][j][q] = 0.f;

    const int KT = K / BBK;

    auto load_tile = [&](int st, int kt) {
        const uint32_t a_s = sbase + st * BSTAGE_BYTES;
        const uint32_t b_s = a_s + BA_BYTES;
        const int kk = kt * BBK;
#pragma unroll
        for (int g = 0; g < 4; g++) {
            int idx = tid + g * 256;
            int r = idx >> 3, c = idx & 7;
            cp_async16(a_s + r * 128 + ((c ^ (r & 7)) << 4),
                       A + (size_t)(bm + r) * K + kk + c * 8);
        }
#pragma unroll
        for (int g = 0; g < 8; g++) {
            int idx = tid + g * 256;
            int r = idx >> 3, c = idx & 7;
            cp_async16(b_s + r * 128 + ((c ^ (r & 7)) << 4),
                       B + (size_t)(bn + r) * K + kk + c * 8);
        }
        cp_commit();
    };

    load_tile(0, 0);
    load_tile(1, 1);
    load_tile(2, 2);
    load_tile(3, 3);

    for (int kt = 0; kt < KT; ++kt) {
        const int st = kt & 3;
        cp_wait<BSTAGES - 1>();
        __syncthreads();

        const uint32_t a_s = sbase + st * BSTAGE_BYTES;
        const uint32_t b_s = a_s + BA_BYTES;

#pragma unroll
        for (int ks = 0; ks < 4; ++ks) {
            uint32_t a[4][4];
#pragma unroll
            for (int mi = 0; mi < 4; mi++) {
                int row = wm * 64 + mi * 16 + (lane & 15);
                int c = ks * 2 + (lane >> 4);
                uint32_t addr = a_s + row * 128 + ((c ^ (row & 7)) << 4);
                asm volatile("ldmatrix.sync.aligned.m8n8.x4.shared.b16 {%0,%1,%2,%3}, [%4];\n"
                             : "=r"(a[mi][0]), "=r"(a[mi][1]), "=r"(a[mi][2]), "=r"(a[mi][3])
                             : "r"(addr));
            }
            uint32_t b[8][2];
#pragma unroll
            for (int nb = 0; nb < 4; nb++) {
                int row = wn * 64 + nb * 16 + (lane & 7) + ((lane >> 4) << 3);
                int c = ks * 2 + ((lane >> 3) & 1);
                uint32_t addr = b_s + row * 128 + ((c ^ (row & 7)) << 4);
                asm volatile("ldmatrix.sync.aligned.m8n8.x4.shared.b16 {%0,%1,%2,%3}, [%4];\n"
                             : "=r"(b[nb * 2][0]), "=r"(b[nb * 2][1]),
                               "=r"(b[nb * 2 + 1][0]), "=r"(b[nb * 2 + 1][1])
                             : "r"(addr));
            }
#pragma unroll
            for (int mi = 0; mi < 4; mi++)
#pragma unroll
                for (int ni = 0; ni < 8; ni++)
                    asm volatile("mma.sync.aligned.m16n8k16.row.col.f32.bf16.bf16.f32 "
                                 "{%0,%1,%2,%3}, {%4,%5,%6,%7}, {%8,%9}, {%0,%1,%2,%3};\n"
                                 : "+f"(acc[mi][ni][0]), "+f"(acc[mi][ni][1]),
                                   "+f"(acc[mi][ni][2]), "+f"(acc[mi][ni][3])
                                 : "r"(a[mi][0]), "r"(a[mi][1]), "r"(a[mi][2]), "r"(a[mi][3]),
                                   "r"(b[ni][0]), "r"(b[ni][1]));
        }

        __syncthreads();
        if (kt + BSTAGES < KT) load_tile(st, kt + BSTAGES);
    }

    const int gid = lane >> 2, tg = lane & 3;

    if (mode == 2) {
        // E = exp(acc) -> bf16 store; per-row sums -> atomicAdd(rs)
        __nv_bfloat16* C = (__nv_bfloat16*)Cout;
#pragma unroll
        for (int mi = 0; mi < 4; mi++) {
            int row = bm + wm * 64 + mi * 16 + gid;
            float s_lo = 0.f, s_hi = 0.f;
#pragma unroll
            for (int ni = 0; ni < 8; ni++) {
                int col = bn + wn * 64 + ni * 8 + tg * 2;
                float e0 = __expf(acc[mi][ni][0]);
                float e1 = __expf(acc[mi][ni][1]);
                float e2 = __expf(acc[mi][ni][2]);
                float e3 = __expf(acc[mi][ni][3]);
                s_lo += e0 + e1;
                s_hi += e2 + e3;
                *reinterpret_cast<__nv_bfloat162*>(&C[(size_t)row * ldc + col]) =
                    __floats2bfloat162_rn(e0, e1);
                *reinterpret_cast<__nv_bfloat162*>(&C[(size_t)(row + 8) * ldc + col]) =
                    __floats2bfloat162_rn(e2, e3);
            }
            // reduce over the 4 lanes sharing this row (tg = lane&3)
            s_lo += __shfl_xor_sync(0xffffffffu, s_lo, 1);
            s_lo += __shfl_xor_sync(0xffffffffu, s_lo, 2);
            s_hi += __shfl_xor_sync(0xffffffffu, s_hi, 1);
            s_hi += __shfl_xor_sync(0xffffffffu, s_hi, 2);
            if (tg == 0) {
                atomicAdd(&rs[row], s_lo);
                atomicAdd(&rs[row + 8], s_hi);
            }
        }
    } else {
        // mode 1: fp32 store, optionally scaled by 1/rs[row]
        float* C = (float*)Cout;
#pragma unroll
        for (int mi = 0; mi < 4; mi++) {
            int row = bm + wm * 64 + mi * 16 + gid;
            float inv_lo = 1.f, inv_hi = 1.f;
            if (rs) {
                inv_lo = 1.f / __ldg(&rs[row]);
                inv_hi = 1.f / __ldg(&rs[row + 8]);
            }
#pragma unroll
            for (int ni = 0; ni < 8; ni++) {
                int col = bn + wn * 64 + ni * 8 + tg * 2;
                C[(size_t)row * ldc + col]           = acc[mi][ni][0] * inv_lo;
                C[(size_t)row * ldc + col + 1]       = acc[mi][ni][1] * inv_lo;
                C[(size_t)(row + 8) * ldc + col]     = acc[mi][ni][2] * inv_hi;
                C[(size_t)(row + 8) * ldc + col + 1] = acc[mi][ni][3] * inv_hi;
            }
        }
    }
}

// ---------------- generic bf16 TN GEMM (mma.sync) for the small prep GEMMs ----------------
#define GBM 128
#define GBN 128
#define GBK 32
#define SSTR 48

__global__ __launch_bounds__(256)
void gemm_tn(const __nv_bfloat16* __restrict__ A, const __nv_bfloat16* __restrict__ B,
             int M, int N, int K, const float* __restrict__ bias, int mode,
             void* __restrict__ Cout, int ldc)
{
    __shared__ __nv_bfloat16 sA[2][GBM * SSTR];
    __shared__ __nv_bfloat16 sB[2][GBN * SSTR];

    const int tid  = threadIdx.x;
    const int lane = tid & 31;
    const int warp = tid >> 5;
    const int wm = warp >> 1;
    const int wn = warp & 1;
    const int bm = blockIdx.y * GBM;
    const int bn = blockIdx.x * GBN;

    const int c0 = tid, c1 = tid + 256;
    const int r0 = c0 >> 2, cc0 = (c0 & 3) * 8;
    const int r1 = c1 >> 2, cc1 = (c1 & 3) * 8;

    float acc[2][8][4];
#pragma unroll
    for (int i = 0; i < 2; i++)
#pragma unroll
        for (int j = 0; j < 8; j++)
#pragma unroll
            for (int q = 0; q < 4; q++) acc[i][j][q] = 0.f;

    const int KT = K / GBK;
    {
        cp_async16(smem_u32(&sA[0][r0 * SSTR + cc0]), A + (size_t)(bm + r0) * K + cc0);
        cp_async16(smem_u32(&sA[0][r1 * SSTR + cc1]), A + (size_t)(bm + r1) * K + cc1);
        cp_async16(smem_u32(&sB[0][r0 * SSTR + cc0]), B + (size_t)(bn + r0) * K + cc0);
        cp_async16(smem_u32(&sB[0][r1 * SSTR + cc1]), B + (size_t)(bn + r1) * K + cc1);
        cp_commit();
    }

    for (int kt = 0; kt < KT; ++kt) {
        const int buf = kt & 1;
        if (kt + 1 < KT) {
            const int k0 = (kt + 1) * GBK;
            const int nb = buf ^ 1;
            cp_async16(smem_u32(&sA[nb][r0 * SSTR + cc0]), A + (size_t)(bm + r0) * K + k0 + cc0);
            cp_async16(smem_u32(&sA[nb][r1 * SSTR + cc1]), A + (size_t)(bm + r1) * K + k0 + cc1);
            cp_async16(smem_u32(&sB[nb][r0 * SSTR + cc0]), B + (size_t)(bn + r0) * K + k0 + cc0);
            cp_async16(smem_u32(&sB[nb][r1 * SSTR + cc1]), B + (size_t)(bn + r1) * K + k0 + cc1);
            cp_commit();
            cp_wait<1>();
        } else {
            cp_wait<0>();
        }
        __syncthreads();

#pragma unroll
        for (int ks = 0; ks < 2; ++ks) {
            uint32_t a[2][4];
#pragma unroll
            for (int mi = 0; mi < 2; mi++) {
                uint32_t addr = smem_u32(&sA[buf][(wm * 32 + mi * 16 + (lane & 15)) * SSTR
                                                  + ks * 16 + (lane >> 4) * 8]);
                asm volatile("ldmatrix.sync.aligned.m8n8.x4.shared.b16 {%0,%1,%2,%3}, [%4];\n"
                             : "=r"(a[mi][0]), "=r"(a[mi][1]), "=r"(a[mi][2]), "=r"(a[mi][3])
                             : "r"(addr));
            }
            uint32_t b[8][2];
#pragma unroll
            for (int nb2 = 0; nb2 < 4; nb2++) {
                int nrow = wn * 64 + nb2 * 16 + (lane & 7) + ((lane >> 4) << 3);
                int kcol = ks * 16 + (((lane >> 3) & 1) << 3);
                uint32_t addr = smem_u32(&sB[buf][nrow * SSTR + kcol]);
                asm volatile("ldmatrix.sync.aligned.m8n8.x4.shared.b16 {%0,%1,%2,%3}, [%4];\n"
                             : "=r"(b[nb2 * 2][0]), "=r"(b[nb2 * 2][1]),
                               "=r"(b[nb2 * 2 + 1][0]), "=r"(b[nb2 * 2 + 1][1])
                             : "r"(addr));
            }
#pragma unroll
            for (int mi = 0; mi < 2; mi++)
#pragma unroll
                for (int ni = 0; ni < 8; ni++)
                    asm volatile("mma.sync.aligned.m16n8k16.row.col.f32.bf16.bf16.f32 "
                                 "{%0,%1,%2,%3}, {%4,%5,%6,%7}, {%8,%9}, {%0,%1,%2,%3};\n"
                                 : "+f"(acc[mi][ni][0]), "+f"(acc[mi][ni][1]),
                                   "+f"(acc[mi][ni][2]), "+f"(acc[mi][ni][3])
                                 : "r"(a[mi][0]), "r"(a[mi][1]), "r"(a[mi][2]), "r"(a[mi][3]),
                                   "r"(b[ni][0]), "r"(b[ni][1]));
        }
        __syncthreads();
    }

    const int gid = lane >> 2, tg = lane & 3;
#pragma unroll
    for (int mi = 0; mi < 2; mi++) {
#pragma unroll
        for (int ni = 0; ni < 8; ni++) {
            int row = bm + wm * 32 + mi * 16 + gid;
            int col = bn + wn * 64 + ni * 8 + tg * 2;
            float v0 = acc[mi][ni][0], v1 = acc[mi][ni][1];
            float v2 = acc[mi][ni][2], v3 = acc[mi][ni][3];
            if (mode == 1) {
                float* C = (float*)Cout;
                float b0 = bias ? bias[col] : 0.f;
                float b1 = bias ? bias[col + 1] : 0.f;
                C[(size_t)row * ldc + col]           = v0 + b0;
                C[(size_t)row * ldc + col + 1]       = v1 + b1;
                C[(size_t)(row + 8) * ldc + col]     = v2 + b0;
                C[(size_t)(row + 8) * ldc + col + 1] = v3 + b1;
            } else {  // mode 2: relu(C + bias), transposed bf16 store
                __nv_bfloat16* C = (__nv_bfloat16*)Cout;
                float b0 = bias[col], b1 = bias[col + 1];
                C[(size_t)col * ldc + row]           = __float2bfloat16(fmaxf(v0 + b0, 0.f));
                C[(size_t)(col + 1) * ldc + row]     = __float2bfloat16(fmaxf(v1 + b1, 0.f));
                C[(size_t)col * ldc + row + 8]       = __float2bfloat16(fmaxf(v2 + b0, 0.f));
                C[(size_t)(col + 1) * ldc + row + 8] = __float2bfloat16(fmaxf(v3 + b1, 0.f));
            }
        }
    }
}

// ---------------- block reduction helpers ----------------
__device__ __forceinline__ float block_reduce_max(float v, float* sred) {
#pragma unroll
    for (int o = 16; o > 0; o >>= 1) v = fmaxf(v, __shfl_xor_sync(0xffffffffu, v, o));
    if ((threadIdx.x & 31) == 0) sred[threadIdx.x >> 5] = v;
    __syncthreads();
    if (threadIdx.x == 0) {
        float m = sred[0];
        for (int w = 1; w < (int)(blockDim.x >> 5); w++) m = fmaxf(m, sred[w]);
        sred[0] = m;
    }
    __syncthreads();
    float r = sred[0];
    __syncthreads();
    return r;
}
__device__ __forceinline__ float block_reduce_sum(float v, float* sred) {
#pragma unroll
    for (int o = 16; o > 0; o >>= 1) v += __shfl_xor_sync(0xffffffffu, v, o);
    if ((threadIdx.x & 31) == 0) sred[threadIdx.x >> 5] = v;
    __syncthreads();
    if (threadIdx.x == 0) {
        float s = sred[0];
        for (int w = 1; w < (int)(blockDim.x >> 5); w++) s += sred[w];
        sred[0] = s;
    }
    __syncthreads();
    float r = sred[0];
    __syncthreads();
    return r;
}

// ---------------- softmax: fp32 logits row -> bf16 (key derivation) ----------------
__global__ __launch_bounds__(256)
void softmax_f32_bf16(const float* __restrict__ in, __nv_bfloat16* __restrict__ out, int ncol) {
    __shared__ float sred[8];
    const float* x = in + (size_t)blockIdx.x * ncol;
    __nv_bfloat16* o = out + (size_t)blockIdx.x * ncol;
    float m = -1e30f;
    for (int i = threadIdx.x; i < ncol; i += blockDim.x) m = fmaxf(m, x[i]);
    m = block_reduce_max(m, sred);
    float s = 0.f;
    for (int i = threadIdx.x; i < ncol; i += blockDim.x) s += __expf(x[i] - m);
    s = block_reduce_sum(s, sred);
    float inv = 1.f / s;
    for (int i = threadIdx.x; i < ncol; i += blockDim.x)
        o[i] = __float2bfloat16(__expf(x[i] - m) * inv);
}

// ---------------- launch ----------------
extern "C" void kernel_launch(void* const* d_in, const int* in_sizes, int n_in,
                              void* d_out, int out_size) {
    const float* k    = (const float*)d_in[0];
    const float* mem  = (const float*)d_in[1];
    const float* fk_w = (const float*)d_in[2];
    const float* fk_b = (const float*)d_in[3];
    const float* fv_w = (const float*)d_in[4];
    const float* fv_b = (const float*)d_in[5];
    float* out = (float*)d_out;

    void *p_kbf, *p_membf, *p_fkw, *p_fvw, *p_keylog, *p_key, *p_valT, *p_S, *p_rs;
    cudaGetSymbolAddress(&p_kbf, g_kbf);
    cudaGetSymbolAddress(&p_membf, g_membf);
    cudaGetSymbolAddress(&p_fkw, g_fkw);
    cudaGetSymbolAddress(&p_fvw, g_fvw);
    cudaGetSymbolAddress(&p_keylog, g_keylog);
    cudaGetSymbolAddress(&p_key, g_key);
    cudaGetSymbolAddress(&p_valT, g_valT);
    cudaGetSymbolAddress(&p_S, g_S);
    cudaGetSymbolAddress(&p_rs, g_rowsum);

    __nv_bfloat16* kbf    = (__nv_bfloat16*)p_kbf;
    __nv_bfloat16* membf  = (__nv_bfloat16*)p_membf;
    __nv_bfloat16* fkwbf  = (__nv_bfloat16*)p_fkw;
    __nv_bfloat16* fvwbf  = (__nv_bfloat16*)p_fvw;
    float*         keylog = (float*)p_keylog;
    __nv_bfloat16* keybf  = (__nv_bfloat16*)p_key;
    __nv_bfloat16* valT   = (__nv_bfloat16*)p_valT;
    __nv_bfloat16* S      = (__nv_bfloat16*)p_S;
    float*         rowsum = (float*)p_rs;

    cudaFuncSetAttribute(gemm_big, cudaFuncAttributeMaxDynamicSharedMemorySize, BDSMEM);

    // converts + rowsum zero
    {
        int n4 = NQ * INP_DIM / 4;
        f32_to_bf16_kernel<<<(n4 + 255) / 256, 256>>>(k, kbf, n4);
        n4 = NUM_MEM * MEM_DIM / 4;
        f32_to_bf16_kernel<<<(n4 + 255) / 256, 256>>>(mem, membf, n4);
        n4 = INP_DIM * MEM_DIM / 4;
        f32_to_bf16_kernel<<<(n4 + 255) / 256, 256>>>(fk_w, fkwbf, n4);
        f32_to_bf16_kernel<<<(n4 + 255) / 256, 256>>>(fv_w, fvwbf, n4);
        zero_f32_kernel<<<NQ / 256, 256>>>(rowsum, NQ);
    }

    // prep: key logits (fp32 + bias), val = relu -> transposed bf16
    {
        dim3 grid(INP_DIM / GBN, NUM_MEM / GBM);
        gemm_tn<<<grid, 256>>>(membf, fkwbf, NUM_MEM, INP_DIM, MEM_DIM, fk_b, 1, keylog, INP_DIM);
        gemm_tn<<<grid, 256>>>(membf, fvwbf, NUM_MEM, INP_DIM, MEM_DIM, fv_b, 2, valT, NUM_MEM);
    }
    softmax_f32_bf16<<<NUM_MEM, 256>>>(keylog, keybf, INP_DIM);

    // E = exp(k @ key^T) [32768, 4096] + row sums (no max subtraction: |logits| < ~0.3)
    {
        dim3 grid(NUM_MEM / BBN, NQ / BBM);   // (16, 256)
        gemm_big<<<grid, 256, BDSMEM>>>(kbf, keybf, INP_DIM, rowsum, 2, S, NUM_MEM);
    }

    // out = (E @ valT^T) / rowsum   [32768, 1024]
    {
        dim3 grid(INP_DIM / BBN, NQ / BBM);   // (4, 256)
        gemm_big<<<grid, 256, BDSMEM>>>(S, valT, NUM_MEM, rowsum, 1, out, INP_DIM);
    }
}